// round 4
// baseline (speedup 1.0000x reference)
#include <cuda_runtime.h>
#include <cuda_fp16.h>
#include <math.h>

// Shapes (fixed by the problem)
#define BB 8
#define TT 512
#define DD 128
#define HH 8

typedef unsigned long long u64;

__device__ __forceinline__ u64 ffma2_(u64 a, u64 b, u64 c) {
    u64 d; asm("fma.rn.f32x2 %0, %1, %2, %3;" : "=l"(d) : "l"(a), "l"(b), "l"(c)); return d;
}
__device__ __forceinline__ u64 pack2_(float x, float y) {
    u64 d; asm("mov.b64 %0, {%1, %2};" : "=l"(d) : "f"(x), "f"(y)); return d;
}
__device__ __forceinline__ float2 unpack2_(u64 v) {
    float2 f; asm("mov.b64 {%0, %1}, %2;" : "=f"(f.x), "=f"(f.y) : "l"(v)); return f;
}

// |a-b| on fp16x2: 1 HSUB2 (fma pipe) + 1 LOP3 (alu pipe)
__device__ __forceinline__ __half2 habsdiff2_(unsigned a, unsigned b) {
    __half2 d = __hsub2(*(__half2*)&a, *(__half2*)&b);
    unsigned u = (*(unsigned*)&d) & 0x7FFF7FFFu;
    return *(__half2*)&u;
}

// Scratch (allocation-free rule: __device__ globals)
__device__ float g_q[BB*HH*TT*DD];   // q[b][h][t][d]
__device__ float g_v[BB*HH*TT*DD];   // v[b][h][s][d]
__device__ float g_o[BB*HH*TT*DD];   // per-head attention output o[b][h][t][d]

// ---------------------------------------------------------------------------
// Kernel 1: QV projection (unchanged from R2; 65us)
// ---------------------------------------------------------------------------
__global__ __launch_bounds__(256) void qv_kernel(const float* __restrict__ x,
                                                 const float* __restrict__ w) {
    extern __shared__ float sm[];
    float* xs = sm;              // 64*128
    float* ws = sm + 64*128;     // 64*132 (padded)
    __shared__ float bsh[64];

    const int tid = threadIdx.x;
    const int tx  = tid & 15, ty = tid >> 4;
    const int m0 = blockIdx.y * 64;
    const int n0 = blockIdx.x * 64;

    const float4* xg = (const float4*)(x + m0*DD);
    for (int i = tid; i < 64*32; i += 256)
        ((float4*)xs)[i] = xg[i];
    for (int i = tid; i < 64*128; i += 256) {
        int r = i >> 7, c = i & 127;
        ws[r*132 + c] = w[(size_t)(n0 + r)*129 + c];
    }
    if (tid < 64) bsh[tid] = w[(size_t)(n0 + tid)*129 + 128];
    __syncthreads();

    u64 acc2[4][4];
#pragma unroll
    for (int i = 0; i < 4; i++)
#pragma unroll
        for (int j = 0; j < 4; j++) acc2[i][j] = 0ULL;

#pragma unroll 4
    for (int k = 0; k < 128; k += 4) {
        ulonglong2 a[4], b[4];
#pragma unroll
        for (int i = 0; i < 4; i++) a[i] = *(const ulonglong2*)&xs[(ty*4 + i)*128 + k];
#pragma unroll
        for (int j = 0; j < 4; j++) b[j] = *(const ulonglong2*)&ws[(tx + 16*j)*132 + k];
#pragma unroll
        for (int i = 0; i < 4; i++)
#pragma unroll
            for (int j = 0; j < 4; j++) {
                acc2[i][j] = ffma2_(a[i].x, b[j].x, acc2[i][j]);
                acc2[i][j] = ffma2_(a[i].y, b[j].y, acc2[i][j]);
            }
    }

#pragma unroll
    for (int i = 0; i < 4; i++) {
        int m  = m0 + ty*4 + i;
        int bi = m >> 9, t = m & 511;
#pragma unroll
        for (int j = 0; j < 4; j++) {
            int o  = n0 + tx + 16*j;
            int hh = o >> 8, c = o & 255;
            float2 f = unpack2_(acc2[i][j]);
            float val = f.x + f.y + bsh[tx + 16*j];
            float* dst = (c < 128) ? g_q : g_v;
            dst[(((size_t)(bi*HH + hh))*TT + t)*DD + (c & 127)] = val;
        }
    }
}

// ---------------------------------------------------------------------------
// Kernel 2: fused L1 attention. Distance loop in fp16 (HSUB2/HADD2): 1 fma-inst
// per element (2x the fp32 FADD path), half2 partials flushed to fp32 every 16 d.
// ---------------------------------------------------------------------------
#define QKSTRIDE 136   // halves per row (272B -> conflict-free quarter-warp phases)

__global__ __launch_bounds__(256) void attn_kernel(const float* __restrict__ x,
                                                   const float* __restrict__ wk,
                                                   const float* __restrict__ msk) {
    extern __shared__ float sm[];
    float*  Ssh   = sm;                          // 64*512 fp32
    __half* qsh_h = (__half*)(sm + 64*512);      // 64*136 halves
    __half* ksh_h = qsh_h + 64*QKSTRIDE;         // 64*136 halves
    float*  vsh   = (float*)(sm + 64*512);       // P@V phase reuses q/k region (64*132 fp32)
    __shared__ float wksh[128];

    const int b  = blockIdx.z, h = blockIdx.y;
    const int t0 = blockIdx.x * 64;
    const int tid = threadIdx.x;
    const int tx  = tid & 15, ty = tid >> 4;

    if (tid < 128) wksh[tid] = wk[h*DD + tid];

    // stage q tile as fp16
    const float4* qg = (const float4*)(g_q + (((size_t)(b*HH + h))*TT + t0)*DD);
    for (int i = tid; i < 64*32; i += 256) {
        int r = i >> 5, c4 = i & 31;
        float4 v = qg[i];
        __half2 h0 = __floats2half2_rn(v.x, v.y);
        __half2 h1 = __floats2half2_rn(v.z, v.w);
        uint2 st; st.x = *(unsigned*)&h0; st.y = *(unsigned*)&h1;
        *(uint2*)&qsh_h[r*QKSTRIDE + c4*4] = st;
    }
    __syncthreads();

    const float NEG_ISQ = -0.08838834764831845f;  // -1/sqrt(128)

    // Phase 1: score tiles (prefetch next x tile into registers)
    float4 kreg[8];
    {
        const float4* xg = (const float4*)(x + ((size_t)b*TT)*DD);
#pragma unroll
        for (int u = 0; u < 8; u++) kreg[u] = xg[tid + u*256];
    }

    for (int s0 = 0; s0 < TT; s0 += 64) {
        // stage k = x*wk as fp16
#pragma unroll
        for (int u = 0; u < 8; u++) {
            int i = tid + u*256;
            int r = i >> 5, c4 = i & 31;
            float4 v = kreg[u];
            v.x *= wksh[c4*4 + 0]; v.y *= wksh[c4*4 + 1];
            v.z *= wksh[c4*4 + 2]; v.w *= wksh[c4*4 + 3];
            __half2 h0 = __floats2half2_rn(v.x, v.y);
            __half2 h1 = __floats2half2_rn(v.z, v.w);
            uint2 st; st.x = *(unsigned*)&h0; st.y = *(unsigned*)&h1;
            *(uint2*)&ksh_h[r*QKSTRIDE + c4*4] = st;
        }
        __syncthreads();

        if (s0 + 64 < TT) {
            const float4* xg = (const float4*)(x + ((size_t)b*TT + s0 + 64)*DD);
#pragma unroll
            for (int u = 0; u < 8; u++) kreg[u] = xg[tid + u*256];
        }

        float2 facc[4][4];
#pragma unroll
        for (int i = 0; i < 4; i++)
#pragma unroll
            for (int j = 0; j < 4; j++) facc[i][j] = make_float2(0.f, 0.f);

#pragma unroll
        for (int it = 0; it < 8; it++) {
            const int d = it * 16;
            __half2 hacc[4][4];
            {
                uint4 qv[4], kv[4];
#pragma unroll
                for (int i = 0; i < 4; i++) qv[i] = *(const uint4*)&qsh_h[(ty*4 + i)*QKSTRIDE + d];
#pragma unroll
                for (int j = 0; j < 4; j++) kv[j] = *(const uint4*)&ksh_h[(tx + 16*j)*QKSTRIDE + d];
#pragma unroll
                for (int i = 0; i < 4; i++)
#pragma unroll
                    for (int j = 0; j < 4; j++) {
                        __half2 a = habsdiff2_(qv[i].x, kv[j].x);
                        a = __hadd2(a, habsdiff2_(qv[i].y, kv[j].y));
                        a = __hadd2(a, habsdiff2_(qv[i].z, kv[j].z));
                        a = __hadd2(a, habsdiff2_(qv[i].w, kv[j].w));
                        hacc[i][j] = a;
                    }
            }
            {
                uint4 qv[4], kv[4];
#pragma unroll
                for (int i = 0; i < 4; i++) qv[i] = *(const uint4*)&qsh_h[(ty*4 + i)*QKSTRIDE + d + 8];
#pragma unroll
                for (int j = 0; j < 4; j++) kv[j] = *(const uint4*)&ksh_h[(tx + 16*j)*QKSTRIDE + d + 8];
#pragma unroll
                for (int i = 0; i < 4; i++)
#pragma unroll
                    for (int j = 0; j < 4; j++) {
                        __half2 a = hacc[i][j];
                        a = __hadd2(a, habsdiff2_(qv[i].x, kv[j].x));
                        a = __hadd2(a, habsdiff2_(qv[i].y, kv[j].y));
                        a = __hadd2(a, habsdiff2_(qv[i].z, kv[j].z));
                        a = __hadd2(a, habsdiff2_(qv[i].w, kv[j].w));
                        hacc[i][j] = a;
                    }
            }
            // flush half2 partials to fp32
#pragma unroll
            for (int i = 0; i < 4; i++)
#pragma unroll
                for (int j = 0; j < 4; j++) {
                    float2 f = __half22float2(hacc[i][j]);
                    facc[i][j].x += f.x;
                    facc[i][j].y += f.y;
                }
        }

#pragma unroll
        for (int i = 0; i < 4; i++)
#pragma unroll
            for (int j = 0; j < 4; j++)
                Ssh[(ty*4 + i)*512 + s0 + tx + 16*j] = (facc[i][j].x + facc[i][j].y) * NEG_ISQ;
        __syncthreads();
    }

    // Phase 2: row softmax + mask  (8 warps, 8 rows each)
    const int warp = tid >> 5, lane = tid & 31;
    for (int r = warp; r < 64; r += 8) {
        float* row = Ssh + r*512;
        float vals[16];
        float m = -1e30f;
#pragma unroll
        for (int i = 0; i < 16; i++) { vals[i] = row[lane + i*32]; m = fmaxf(m, vals[i]); }
#pragma unroll
        for (int o = 16; o > 0; o >>= 1) m = fmaxf(m, __shfl_xor_sync(0xffffffffu, m, o));
        float sum = 0.f;
#pragma unroll
        for (int i = 0; i < 16; i++) { vals[i] = __expf(vals[i] - m); sum += vals[i]; }
#pragma unroll
        for (int o = 16; o > 0; o >>= 1) sum += __shfl_xor_sync(0xffffffffu, sum, o);
        float inv = 1.f / sum;
        const float* mrow = msk + ((size_t)(h*TT + t0 + r))*TT;
#pragma unroll
        for (int i = 0; i < 16; i++)
            row[lane + i*32] = vals[i] * inv * mrow[lane + i*32];
    }
    __syncthreads();

    // Phase 3: O = P @ V  (fp32, FFMA2-packed across d; reuse q/k region)
    u64 oacc2[4][4];
#pragma unroll
    for (int i = 0; i < 4; i++)
#pragma unroll
        for (int j = 0; j < 4; j++) oacc2[i][j] = 0ULL;

    float4 vreg[8];
    {
        const float4* vg = (const float4*)(g_v + (((size_t)(b*HH + h))*TT)*DD);
#pragma unroll
        for (int u = 0; u < 8; u++) vreg[u] = vg[tid + u*256];
    }

    for (int s0 = 0; s0 < TT; s0 += 64) {
#pragma unroll
        for (int u = 0; u < 8; u++) {
            int i = tid + u*256;
            int r = i >> 5, c4 = i & 31;
            *(float4*)&vsh[r*132 + c4*4] = vreg[u];
        }
        __syncthreads();

        if (s0 + 64 < TT) {
            const float4* vg = (const float4*)(g_v + (((size_t)(b*HH + h))*TT + s0 + 64)*DD);
#pragma unroll
            for (int u = 0; u < 8; u++) vreg[u] = vg[tid + u*256];
        }

#pragma unroll 4
        for (int s = 0; s < 64; s++) {
            u64 pp[4];
#pragma unroll
            for (int i = 0; i < 4; i++) {
                float p = Ssh[(ty*4 + i)*512 + s0 + s];
                pp[i] = pack2_(p, p);
            }
            ulonglong2 v0 = *(const ulonglong2*)&vsh[s*132 + tx*4];
            ulonglong2 v1 = *(const ulonglong2*)&vsh[s*132 + 64 + tx*4];
#pragma unroll
            for (int i = 0; i < 4; i++) {
                oacc2[i][0] = ffma2_(pp[i], v0.x, oacc2[i][0]);
                oacc2[i][1] = ffma2_(pp[i], v0.y, oacc2[i][1]);
                oacc2[i][2] = ffma2_(pp[i], v1.x, oacc2[i][2]);
                oacc2[i][3] = ffma2_(pp[i], v1.y, oacc2[i][3]);
            }
        }
        __syncthreads();
    }

    float* og = g_o + (((size_t)(b*HH + h))*TT + t0)*DD;
#pragma unroll
    for (int i = 0; i < 4; i++) {
        int r = ty*4 + i;
        ulonglong2 w0, w1;
        w0.x = oacc2[i][0]; w0.y = oacc2[i][1];
        w1.x = oacc2[i][2]; w1.y = oacc2[i][3];
        *(ulonglong2*)&og[r*DD + tx*4]      = w0;
        *(ulonglong2*)&og[r*DD + 64 + tx*4] = w1;
    }
}

// ---------------------------------------------------------------------------
// Kernel 3: head-reduce + quickGELU + fanout + residual (unchanged from R2)
// ---------------------------------------------------------------------------
__global__ __launch_bounds__(256) void final_kernel(const float* __restrict__ x,
                                                    const float* __restrict__ fw,
                                                    float* __restrict__ out) {
    extern __shared__ float sm[];
    float* Wsh  = sm;            // 128*130
    float* yosh = sm + 128*130;  // 16*128

    const int b = blockIdx.y, t0 = blockIdx.x * 16;
    const int tid = threadIdx.x;

    for (int i = tid; i < 128*129; i += 256) {
        int r = i / 129, c = i - r*129;
        Wsh[r*130 + c] = fw[i];
    }

    for (int i = tid; i < 16*128; i += 256) {
        int r = i >> 7, dd = i & 127;
        float bo = 0.f;
#pragma unroll
        for (int h = 0; h < HH; h++)
            bo += g_o[(((size_t)(b*HH + h))*TT + t0 + r)*DD + dd];
        float z  = bo + 4.5f;
        float sg = 1.f / (1.f + __expf(-1.702f * z));
        yosh[r*128 + dd] = z*sg - 4.5f;
    }
    __syncthreads();

    const int o = tid & 127, half = tid >> 7;
    u64 acc2[8];
#pragma unroll
    for (int rr = 0; rr < 8; rr++) acc2[rr] = 0ULL;

#pragma unroll 4
    for (int i = 0; i < 128; i += 2) {
        u64 w2 = *(const u64*)&Wsh[o*130 + i];
#pragma unroll
        for (int rr = 0; rr < 8; rr++)
            acc2[rr] = ffma2_(w2, *(const u64*)&yosh[(half*8 + rr)*128 + i], acc2[rr]);
    }
    float bias = Wsh[o*130 + 128];
#pragma unroll
    for (int rr = 0; rr < 8; rr++) {
        int t = t0 + half*8 + rr;
        size_t idx = ((size_t)b*TT + t)*DD + o;
        float2 f = unpack2_(acc2[rr]);
        out[idx] = x[idx] + f.x + f.y + bias;
    }
}

// ---------------------------------------------------------------------------
extern "C" void kernel_launch(void* const* d_in, const int* in_sizes, int n_in,
                              void* d_out, int out_size) {
    const float* x   = (const float*)d_in[0];
    const float* msk = (const float*)d_in[1];
    const float* wqv = (const float*)d_in[2];
    const float* wk  = (const float*)d_in[3];
    const float* fw  = (const float*)d_in[4];
    float* out = (float*)d_out;

    const int attn_smem = 64*512*4 + 2*64*QKSTRIDE*2;  // 165888 B

    cudaFuncSetAttribute(qv_kernel,    cudaFuncAttributeMaxDynamicSharedMemorySize,
                         (64*128 + 64*132) * 4);
    cudaFuncSetAttribute(attn_kernel,  cudaFuncAttributeMaxDynamicSharedMemorySize,
                         attn_smem);
    cudaFuncSetAttribute(final_kernel, cudaFuncAttributeMaxDynamicSharedMemorySize,
                         (128*130 + 16*128) * 4);

    qv_kernel<<<dim3(32, 64), 256, (64*128 + 64*132) * 4>>>(x, wqv);
    attn_kernel<<<dim3(TT/64, HH, BB), 256, attn_smem>>>(x, wk, msk);
    final_kernel<<<dim3(TT/16, BB), 256, (128*130 + 16*128) * 4>>>(x, fw, out);
}

// round 6
// speedup vs baseline: 1.8895x; 1.8895x over previous
#include <cuda_runtime.h>
#include <cuda_fp16.h>
#include <math.h>
#include <cstdint>

#define BB 8
#define TT 512
#define DD 128
#define HH 8

typedef unsigned long long u64;

__device__ __forceinline__ u64 ffma2_(u64 a, u64 b, u64 c) {
    u64 d; asm("fma.rn.f32x2 %0, %1, %2, %3;" : "=l"(d) : "l"(a), "l"(b), "l"(c)); return d;
}
__device__ __forceinline__ float2 unpack2_(u64 v) {
    float2 f; asm("mov.b64 {%0, %1}, %2;" : "=f"(f.x), "=f"(f.y) : "l"(v)); return f;
}

// m16n8k16 f16 MMA, fp32 accumulate (portable PTX, runs on sm_103 HMMA)
__device__ __forceinline__ void mma16816_(float* c, const unsigned* a, const unsigned* b) {
    asm volatile(
        "mma.sync.aligned.m16n8k16.row.col.f32.f16.f16.f32 "
        "{%0,%1,%2,%3}, {%4,%5,%6,%7}, {%8,%9}, {%0,%1,%2,%3};"
        : "+f"(c[0]), "+f"(c[1]), "+f"(c[2]), "+f"(c[3])
        : "r"(a[0]), "r"(a[1]), "r"(a[2]), "r"(a[3]), "r"(b[0]), "r"(b[1]));
}

// Scratch
__device__ float  g_q [BB*HH*TT*DD];          // q[b][h][t][d] fp32
__device__ __half g_vT[(size_t)BB*HH*DD*TT];  // vT[b][h][d][s] fp16
__device__ float  g_o [BB*HH*TT*DD];          // o[b][h][t][d] fp32

// ---------------------------------------------------------------------------
// Kernel 1: QV projection (R2 f32x2 GEMM; v written transposed as fp16)
// ---------------------------------------------------------------------------
__global__ __launch_bounds__(256) void qv_kernel(const float* __restrict__ x,
                                                 const float* __restrict__ w) {
    extern __shared__ float sm[];
    float* xs = sm;              // 64*128
    float* ws = sm + 64*128;     // 64*132
    __shared__ float bsh[64];

    const int tid = threadIdx.x;
    const int tx  = tid & 15, ty = tid >> 4;
    const int m0 = blockIdx.y * 64;
    const int n0 = blockIdx.x * 64;

    const float4* xg = (const float4*)(x + m0*DD);
    for (int i = tid; i < 64*32; i += 256)
        ((float4*)xs)[i] = xg[i];
    for (int i = tid; i < 64*128; i += 256) {
        int r = i >> 7, c = i & 127;
        ws[r*132 + c] = w[(size_t)(n0 + r)*129 + c];
    }
    if (tid < 64) bsh[tid] = w[(size_t)(n0 + tid)*129 + 128];
    __syncthreads();

    u64 acc2[4][4];
#pragma unroll
    for (int i = 0; i < 4; i++)
#pragma unroll
        for (int j = 0; j < 4; j++) acc2[i][j] = 0ULL;

#pragma unroll 4
    for (int k = 0; k < 128; k += 4) {
        ulonglong2 a[4], b[4];
#pragma unroll
        for (int i = 0; i < 4; i++) a[i] = *(const ulonglong2*)&xs[(ty*4 + i)*128 + k];
#pragma unroll
        for (int j = 0; j < 4; j++) b[j] = *(const ulonglong2*)&ws[(tx + 16*j)*132 + k];
#pragma unroll
        for (int i = 0; i < 4; i++)
#pragma unroll
            for (int j = 0; j < 4; j++) {
                acc2[i][j] = ffma2_(a[i].x, b[j].x, acc2[i][j]);
                acc2[i][j] = ffma2_(a[i].y, b[j].y, acc2[i][j]);
            }
    }

#pragma unroll
    for (int i = 0; i < 4; i++) {
        int m  = m0 + ty*4 + i;
        int bi = m >> 9, t = m & 511;
#pragma unroll
        for (int j = 0; j < 4; j++) {
            int o  = n0 + tx + 16*j;
            int hh = o >> 8, c = o & 255;
            float2 f = unpack2_(acc2[i][j]);
            float val = f.x + f.y + bsh[tx + 16*j];
            if (c < 128)
                g_q[(((size_t)(bi*HH + hh))*TT + t)*DD + c] = val;
            else
                g_vT[(((size_t)(bi*HH + hh))*DD + (c - 128))*TT + t] = __float2half(val);
        }
    }
}

// ---------------------------------------------------------------------------
// Kernel 2: fused L1 attention. fp32 distance + mma.sync (HMMA) P@V.
// Dynamic smem (bytes):
//   [0,133120)        Ssh f32 64 x (stride 520)
//   [133120,166912)   phase1 qsh f32 64x132  | phase3 vTsh fp16 128x136 (34816B)
//   [166912,200704)   phase1 ksh f32 64x132  | (tail of vTsh overlays start)
// ---------------------------------------------------------------------------
#define SSTRIDE 520
#define ATTN_SMEM 200704
#define OFF_Q  133120
#define OFF_K  166912
#define OFF_VT 133120

__global__ __launch_bounds__(256) void attn_kernel(const float* __restrict__ x,
                                                   const float* __restrict__ wk,
                                                   const float* __restrict__ msk) {
    extern __shared__ char smc[];
    float* Ssh = (float*)smc;
    float* qsh = (float*)(smc + OFF_Q);
    float* ksh = (float*)(smc + OFF_K);
    __shared__ float wksh[128];

    const int b  = blockIdx.z, h = blockIdx.y;
    const int t0 = blockIdx.x * 64;
    const int tid = threadIdx.x;
    const int tx  = tid & 15, ty = tid >> 4;

    if (tid < 128) wksh[tid] = wk[h*DD + tid];

    // stage q tile
    const float4* qg = (const float4*)(g_q + (((size_t)(b*HH + h))*TT + t0)*DD);
    for (int i = tid; i < 64*32; i += 256) {
        int r = i >> 5, c4 = i & 31;
        *(float4*)&qsh[r*132 + c4*4] = qg[i];
    }
    __syncthreads();

    const float NEG_ISQ = -0.08838834764831845f;  // -1/sqrt(128)

    // ---------------- Phase 1: score tiles (fp32, at the fma-pipe floor) ----
    float4 kreg[8];
    {
        const float4* xg = (const float4*)(x + ((size_t)b*TT)*DD);
#pragma unroll
        for (int u = 0; u < 8; u++) kreg[u] = xg[tid + u*256];
    }

    for (int s0 = 0; s0 < TT; s0 += 64) {
#pragma unroll
        for (int u = 0; u < 8; u++) {
            int i = tid + u*256;
            int r = i >> 5, c4 = i & 31;
            float4 v = kreg[u];
            v.x *= wksh[c4*4 + 0]; v.y *= wksh[c4*4 + 1];
            v.z *= wksh[c4*4 + 2]; v.w *= wksh[c4*4 + 3];
            *(float4*)&ksh[r*132 + c4*4] = v;
        }
        __syncthreads();

        if (s0 + 64 < TT) {
            const float4* xg = (const float4*)(x + ((size_t)b*TT + s0 + 64)*DD);
#pragma unroll
            for (int u = 0; u < 8; u++) kreg[u] = xg[tid + u*256];
        }

        float acc[4][4];
#pragma unroll
        for (int i = 0; i < 4; i++)
#pragma unroll
            for (int j = 0; j < 4; j++) acc[i][j] = 0.f;

#pragma unroll 4
        for (int d = 0; d < 128; d += 4) {
            float4 qv[4], kv[4];
#pragma unroll
            for (int i = 0; i < 4; i++) qv[i] = *(const float4*)&qsh[(ty*4 + i)*132 + d];
#pragma unroll
            for (int j = 0; j < 4; j++) kv[j] = *(const float4*)&ksh[(tx + 16*j)*132 + d];
#pragma unroll
            for (int i = 0; i < 4; i++)
#pragma unroll
                for (int j = 0; j < 4; j++) {
                    acc[i][j] += fabsf(qv[i].x - kv[j].x) + fabsf(qv[i].y - kv[j].y)
                               + fabsf(qv[i].z - kv[j].z) + fabsf(qv[i].w - kv[j].w);
                }
        }
#pragma unroll
        for (int i = 0; i < 4; i++)
#pragma unroll
            for (int j = 0; j < 4; j++)
                Ssh[(ty*4 + i)*SSTRIDE + s0 + tx + 16*j] = acc[i][j] * NEG_ISQ;
        __syncthreads();
    }

    // ---------------- Phase 2: row softmax + mask ----------------
    const int warp = tid >> 5, lane = tid & 31;
    for (int r = warp; r < 64; r += 8) {
        float* row = Ssh + r*SSTRIDE;
        float vals[16];
        float m = -1e30f;
#pragma unroll
        for (int i = 0; i < 16; i++) { vals[i] = row[lane + i*32]; m = fmaxf(m, vals[i]); }
#pragma unroll
        for (int o = 16; o > 0; o >>= 1) m = fmaxf(m, __shfl_xor_sync(0xffffffffu, m, o));
        float sum = 0.f;
#pragma unroll
        for (int i = 0; i < 16; i++) { vals[i] = __expf(vals[i] - m); sum += vals[i]; }
#pragma unroll
        for (int o = 16; o > 0; o >>= 1) sum += __shfl_xor_sync(0xffffffffu, sum, o);
        float inv = 1.f / sum;
        const float* mrow = msk + ((size_t)(h*TT + t0 + r))*TT;
#pragma unroll
        for (int i = 0; i < 16; i++)
            row[lane + i*32] = vals[i] * inv * mrow[lane + i*32];
    }
    __syncthreads();

    // ---------------- Phase 3: O = P @ V via mma.sync ----------------
    // Warp w: m-tile mt=w&3 (16 t-rows), n-group ng=w>>2 (64 d-cols, 8 n-tiles)
    __half* vTsh = (__half*)(smc + OFF_VT);
    const __half* vTg = g_vT + ((size_t)(b*HH + h))*DD*TT;
    const int mt = warp & 3, ng = warp >> 2;
    const int g = lane >> 2, tg = lane & 3;

    float oacc[8][4];
#pragma unroll
    for (int nt = 0; nt < 8; nt++)
#pragma unroll
        for (int c = 0; c < 4; c++) oacc[nt][c] = 0.f;

    for (int sc = 0; sc < 4; sc++) {
        const int s0 = sc * 128;
        // stage vT chunk [128 d][128 s] fp16, row stride 136 halves
        for (int i = tid; i < 2048; i += 256) {
            int r = i >> 4, kg = i & 15;
            uint4 val = *(const uint4*)(vTg + (size_t)r*TT + s0 + kg*8);
            *(uint4*)&vTsh[r*136 + kg*8] = val;
        }
        __syncthreads();

#pragma unroll
        for (int kk = 0; kk < 8; kk++) {
            // A fragment: P rows mt*16+g(+8), k-cols s0+kk*16+tg*2 (+1,+8)
            const int ar = (mt*16 + g)*SSTRIDE + s0 + kk*16 + tg*2;
            float2 a01 = *(const float2*)&Ssh[ar];
            float2 a23 = *(const float2*)&Ssh[ar + 8*SSTRIDE];
            float2 a45 = *(const float2*)&Ssh[ar + 8];
            float2 a67 = *(const float2*)&Ssh[ar + 8*SSTRIDE + 8];
            unsigned af[4];
            __half2 h0 = __floats2half2_rn(a01.x, a01.y); af[0] = *(unsigned*)&h0;
            __half2 h1 = __floats2half2_rn(a23.x, a23.y); af[1] = *(unsigned*)&h1;
            __half2 h2 = __floats2half2_rn(a45.x, a45.y); af[2] = *(unsigned*)&h2;
            __half2 h3 = __floats2half2_rn(a67.x, a67.y); af[3] = *(unsigned*)&h3;

            const int kb = kk*16 + tg*2;
#pragma unroll
            for (int nt = 0; nt < 8; nt++) {
                int row = ng*64 + nt*8 + g;
                unsigned bf[2];
                bf[0] = *(const unsigned*)&vTsh[row*136 + kb];
                bf[1] = *(const unsigned*)&vTsh[row*136 + kb + 8];
                mma16816_(oacc[nt], af, bf);
            }
        }
        __syncthreads();
    }

    // write O tile: rows t0+mt*16+g(+8), cols ng*64+nt*8+tg*2(+1)
    float* og = g_o + (((size_t)(b*HH + h))*TT + t0)*DD;
#pragma unroll
    for (int nt = 0; nt < 8; nt++) {
        int d = ng*64 + nt*8 + tg*2;
        int r0 = mt*16 + g;
        *(float2*)&og[(size_t)r0*DD + d]       = make_float2(oacc[nt][0], oacc[nt][1]);
        *(float2*)&og[(size_t)(r0 + 8)*DD + d] = make_float2(oacc[nt][2], oacc[nt][3]);
    }
}

// ---------------------------------------------------------------------------
// Kernel 3: head-reduce + quickGELU + fanout + residual (R2 version)
// ---------------------------------------------------------------------------
__global__ __launch_bounds__(256) void final_kernel(const float* __restrict__ x,
                                                    const float* __restrict__ fw,
                                                    float* __restrict__ out) {
    extern __shared__ float sm[];
    float* Wsh  = sm;            // 128*130
    float* yosh = sm + 128*130;  // 16*128

    const int b = blockIdx.y, t0 = blockIdx.x * 16;
    const int tid = threadIdx.x;

    for (int i = tid; i < 128*129; i += 256) {
        int r = i / 129, c = i - r*129;
        Wsh[r*130 + c] = fw[i];
    }

    for (int i = tid; i < 16*128; i += 256) {
        int r = i >> 7, dd = i & 127;
        float bo = 0.f;
#pragma unroll
        for (int h = 0; h < HH; h++)
            bo += g_o[(((size_t)(b*HH + h))*TT + t0 + r)*DD + dd];
        float z  = bo + 4.5f;
        float sg = 1.f / (1.f + __expf(-1.702f * z));
        yosh[r*128 + dd] = z*sg - 4.5f;
    }
    __syncthreads();

    const int o = tid & 127, half = tid >> 7;
    u64 acc2[8];
#pragma unroll
    for (int rr = 0; rr < 8; rr++) acc2[rr] = 0ULL;

#pragma unroll 4
    for (int i = 0; i < 128; i += 2) {
        u64 w2 = *(const u64*)&Wsh[o*130 + i];
#pragma unroll
        for (int rr = 0; rr < 8; rr++)
            acc2[rr] = ffma2_(w2, *(const u64*)&yosh[(half*8 + rr)*128 + i], acc2[rr]);
    }
    float bias = Wsh[o*130 + 128];
#pragma unroll
    for (int rr = 0; rr < 8; rr++) {
        int t = t0 + half*8 + rr;
        size_t idx = ((size_t)b*TT + t)*DD + o;
        float2 f = unpack2_(acc2[rr]);
        out[idx] = x[idx] + f.x + f.y + bias;
    }
}

// ---------------------------------------------------------------------------
extern "C" void kernel_launch(void* const* d_in, const int* in_sizes, int n_in,
                              void* d_out, int out_size) {
    const float* x   = (const float*)d_in[0];
    const float* msk = (const float*)d_in[1];
    const float* wqv = (const float*)d_in[2];
    const float* wk  = (const float*)d_in[3];
    const float* fw  = (const float*)d_in[4];
    float* out = (float*)d_out;

    cudaFuncSetAttribute(qv_kernel,    cudaFuncAttributeMaxDynamicSharedMemorySize,
                         (64*128 + 64*132) * 4);
    cudaFuncSetAttribute(attn_kernel,  cudaFuncAttributeMaxDynamicSharedMemorySize,
                         ATTN_SMEM);
    cudaFuncSetAttribute(final_kernel, cudaFuncAttributeMaxDynamicSharedMemorySize,
                         (128*130 + 16*128) * 4);

    qv_kernel<<<dim3(32, 64), 256, (64*128 + 64*132) * 4>>>(x, wqv);
    attn_kernel<<<dim3(TT/64, HH, BB), 256, ATTN_SMEM>>>(x, wk, msk);
    final_kernel<<<dim3(TT/16, BB), 256, (128*130 + 16*128) * 4>>>(x, fw, out);
}